// round 2
// baseline (speedup 1.0000x reference)
#include <cuda_runtime.h>
#include <cstdint>

// Problem constants
#define NBATCH 8
#define CDIM   256
#define TDIM   16384
#define DCODES 512

// Tiling
#define BT 128          // t (queries) per block
#define BD 64           // codes per smem chunk
#define NTHREADS 256

// smem layout (floats)
#define XS_STRIDE 128                    // xs[c][t], 512B rows
#define RT_STRIDE 132                    // rowsT[c][t] padded (epilogue overlay of xs)
#define REGION_A_FLOATS (CDIM * RT_STRIDE)   // 33792 floats = 135168 B (>= xs size)
#define WS_STRIDE 68                     // ws[c][dl] padded, 272B rows (16B-aligned)
#define REGION_B_FLOATS (CDIM * WS_STRIDE)   // 17408 floats = 69632 B
#define SMEM_BYTES ((REGION_A_FLOATS + REGION_B_FLOATS) * 4)  // 204800 B

__device__ float g_hnorm[DCODES];

// ---------------------------------------------------------------------------
// Prologue: hnorm[d] = 0.5 * ||w_d||^2
// ---------------------------------------------------------------------------
__global__ void vq_hnorm_kernel(const float* __restrict__ dict) {
    int d = blockIdx.x * blockDim.x + threadIdx.x;
    if (d < DCODES) {
        const float4* row = reinterpret_cast<const float4*>(dict + (size_t)d * CDIM);
        float s = 0.f;
#pragma unroll
        for (int q = 0; q < CDIM / 4; q++) {
            float4 v = row[q];
            s += v.x * v.x + v.y * v.y + v.z * v.z + v.w * v.w;
        }
        g_hnorm[d] = 0.5f * s;
    }
}

// ---------------------------------------------------------------------------
// Packed f32x2 helpers (Blackwell dual-rate fp32)
// ---------------------------------------------------------------------------
__device__ __forceinline__ unsigned long long pack2(float x, float y) {
    unsigned long long r;
    asm("mov.b64 %0, {%1, %2};" : "=l"(r) : "f"(x), "f"(y));
    return r;
}
__device__ __forceinline__ void fma2(unsigned long long& d,
                                     unsigned long long a, unsigned long long b) {
    asm("fma.rn.f32x2 %0, %1, %2, %0;" : "+l"(d) : "l"(a), "l"(b));
}
__device__ __forceinline__ float2 unpack2(unsigned long long v) {
    float2 r;
    asm("mov.b64 {%0, %1}, %2;" : "=f"(r.x), "=f"(r.y) : "l"(v));
    return r;
}

// ---------------------------------------------------------------------------
// Main kernel: one block = 128 queries (one n, contiguous t) vs all 512 codes
// score_d = dot(x, w_d) - 0.5*||w_d||^2 ; argmax == reference argmin
// ---------------------------------------------------------------------------
__global__ __launch_bounds__(NTHREADS, 1)
void vq_main_kernel(const float* __restrict__ inputs,
                    const float* __restrict__ dict,
                    float* __restrict__ out) {
    extern __shared__ float smem[];
    float* xs = smem;                         // [CDIM][XS_STRIDE]
    float* ws = smem + REGION_A_FLOATS;       // [CDIM][WS_STRIDE]
    // reduction overlay (region B, after all compute chunks):
    float* s_red = ws;                        // [BT][16]
    int*   i_red = reinterpret_cast<int*>(ws + BT * 16);   // [BT][16]
    int*   fidx  = reinterpret_cast<int*>(ws + 2 * BT * 16); // [BT]

    const int tid = threadIdx.x;
    const int blk = blockIdx.x;
    const int tiles_per_n = TDIM / BT;        // 128
    const int n   = blk / tiles_per_n;
    const int tt0 = (blk % tiles_per_n) * BT;

    // ---- Stage x tile: xs[c][t] = inputs[n][c][tt0+t] (coalesced float4) ----
    {
        const float* xin = inputs + ((size_t)n * CDIM) * TDIM + tt0;
        int lane = tid & 31, wrow = tid >> 5;
#pragma unroll
        for (int j = 0; j < 32; j++) {
            int c = wrow + 8 * j;
            float4 v = *reinterpret_cast<const float4*>(xin + (size_t)c * TDIM + 4 * lane);
            *reinterpret_cast<float4*>(&xs[c * XS_STRIDE + 4 * lane]) = v;
        }
    }

    const int ti = tid & 15;   // t-group: owns t in {4ti..4ti+3} u {64+4ti..64+4ti+3}
    const int di = tid >> 4;   // d-group: owns d_local in {4di..4di+3} per chunk

    float best[8];
    int   bidx[8];
#pragma unroll
    for (int j = 0; j < 8; j++) { best[j] = -3.0e38f; bidx[j] = 0; }

    for (int d0 = 0; d0 < DCODES; d0 += BD) {
        __syncthreads();  // prior chunk compute done (and x staging done on iter 0)

        // Stage w chunk: ws[c][dl] = dict[d0+dl][c]  (coalesced LDG, 4-way STS)
#pragma unroll 8
        for (int j = 0; j < BD; j++) {
            float v = dict[(size_t)(d0 + j) * CDIM + tid];
            ws[tid * WS_STRIDE + j] = v;
        }
        __syncthreads();

        // ---- GEMM micro-tile: 8t x 4d per thread, f32x2 pairs over t ----
        unsigned long long acc[4][4];
#pragma unroll
        for (int p = 0; p < 4; p++)
#pragma unroll
            for (int k = 0; k < 4; k++) acc[p][k] = 0ull;

        const float* xrow0 = xs + ti * 4;
        const float* xrow1 = xs + 64 + ti * 4;
        const float* wrow  = ws + di * 4;

#pragma unroll 8
        for (int c = 0; c < CDIM; c++) {
            ulonglong2 xa = *reinterpret_cast<const ulonglong2*>(xrow0 + c * XS_STRIDE);
            ulonglong2 xb = *reinterpret_cast<const ulonglong2*>(xrow1 + c * XS_STRIDE);
            float4 wv = *reinterpret_cast<const float4*>(wrow + c * WS_STRIDE);
            unsigned long long w0 = pack2(wv.x, wv.x);
            unsigned long long w1 = pack2(wv.y, wv.y);
            unsigned long long w2 = pack2(wv.z, wv.z);
            unsigned long long w3 = pack2(wv.w, wv.w);
            fma2(acc[0][0], xa.x, w0); fma2(acc[0][1], xa.x, w1);
            fma2(acc[0][2], xa.x, w2); fma2(acc[0][3], xa.x, w3);
            fma2(acc[1][0], xa.y, w0); fma2(acc[1][1], xa.y, w1);
            fma2(acc[1][2], xa.y, w2); fma2(acc[1][3], xa.y, w3);
            fma2(acc[2][0], xb.x, w0); fma2(acc[2][1], xb.x, w1);
            fma2(acc[2][2], xb.x, w2); fma2(acc[2][3], xb.x, w3);
            fma2(acc[3][0], xb.y, w0); fma2(acc[3][1], xb.y, w1);
            fma2(acc[3][2], xb.y, w2); fma2(acc[3][3], xb.y, w3);
        }

        // ---- Finalize chunk: score = dot - hnorm, running argmax ----
#pragma unroll
        for (int k = 0; k < 4; k++) {
            int d = d0 + di * 4 + k;
            float hn = __ldg(&g_hnorm[d]);
#pragma unroll
            for (int p = 0; p < 4; p++) {
                float2 s = unpack2(acc[p][k]);
                float v0 = s.x - hn;
                float v1 = s.y - hn;
                int j0 = 2 * p, j1 = 2 * p + 1;
                if (v0 > best[j0]) { best[j0] = v0; bidx[j0] = d; }
                if (v1 > best[j1]) { best[j1] = v1; bidx[j1] = d; }
            }
        }
    }

    __syncthreads();  // all compute reads of ws done before overlay

    // ---- Cross-thread (over di) argmax reduction per t ----
#pragma unroll
    for (int j = 0; j < 8; j++) {
        int t = (j < 4) ? (ti * 4 + j) : (64 + ti * 4 + (j - 4));
        s_red[t * 16 + di] = best[j];
        i_red[t * 16 + di] = bidx[j];
    }
    __syncthreads();

    const size_t E = (size_t)NBATCH * CDIM * TDIM;
    if (tid < BT) {
        float bs = -3.0e38f; int bi = 0x7fffffff;
        for (int q = 0; q < 16; q++) {
            float s = s_red[tid * 16 + q];
            int  ix = i_red[tid * 16 + q];
            if (s > bs || (s == bs && ix < bi)) { bs = s; bi = ix; }
        }
        fidx[tid] = bi;
        // idxs output (as float, exact for idx < 512)
        out[2 * E + (size_t)n * TDIM + tt0 + tid] = (float)bi;
    }
    __syncthreads();

    // ---- Stage selected dict rows transposed: rowsT[c][t] (overlay region A) ----
    {
        float* rowsT = smem;
        int lane = tid & 31, w = tid >> 5;
        for (int t = w; t < BT; t += 8) {
            const float* drow = dict + (size_t)fidx[t] * CDIM;
#pragma unroll
            for (int q = 0; q < CDIM; q += 32) {
                float v = drow[q + lane];          // coalesced LDG (dict hot in L2)
                rowsT[(q + lane) * RT_STRIDE + t] = v;  // 4-way STS, small volume
            }
        }
    }
    __syncthreads();

    // ---- Write embedded + passthrough, float4-coalesced over t ----
    {
        const float* rowsT = smem;
        float* out_e = out;
        float* out_p = out + E;
        int g = tid & 31, cw = tid >> 5;
#pragma unroll
        for (int j = 0; j < 32; j++) {
            int c = cw + 8 * j;
            float4 v = *reinterpret_cast<const float4*>(&rowsT[c * RT_STRIDE + 4 * g]);
            size_t o = ((size_t)n * CDIM + c) * TDIM + tt0 + 4 * g;
            *reinterpret_cast<float4*>(out_e + o) = v;
            *reinterpret_cast<float4*>(out_p + o) = v;
        }
    }
}

// ---------------------------------------------------------------------------
extern "C" void kernel_launch(void* const* d_in, const int* in_sizes, int n_in,
                              void* d_out, int out_size) {
    const float* inputs = (const float*)d_in[0];
    const float* dict   = (const float*)d_in[1];
    float* out = (float*)d_out;

    cudaFuncSetAttribute(vq_main_kernel,
                         cudaFuncAttributeMaxDynamicSharedMemorySize, SMEM_BYTES);

    vq_hnorm_kernel<<<4, 128>>>(dict);
    vq_main_kernel<<<(NBATCH * TDIM) / BT, NTHREADS, SMEM_BYTES>>>(inputs, dict, out);
}

// round 4
// speedup vs baseline: 2.2429x; 2.2429x over previous
#include <cuda_runtime.h>
#include <cuda_bf16.h>
#include <cstdint>

#define NBATCH 8
#define CDIM   256
#define TDIM   16384
#define DCODES 512
#define BT     128
#define NTHREADS 256
#define MARGIN 4.0e-3f

// ---- smem byte layout ----
// A region: Ah[4 kchunks][128 t][72 bf16] then Am[4][128][72]; row stride 144 B
#define AK        18432                 // one split, one kchunk: 128*144
#define OFF_AM    73728                 // Am base = 4*AK
#define OFF_B     147456                // B double buffer region
#define BSTAGE    36864                 // per stage: Bh 18432 + Bm 18432
#define OFF_FIDX  221184
#define OFF_SIDXM 221696
#define OFF_FLAGS 222208
#define OFF_FLAGN 222720
#define SMEM_BYTES 223232
// overlays (A region, dead after mainloop):
//   bestv f[128][16]@0  secv@8192  ibest@16384  isec@24576 ; later rowsT[256][132] f32 @0
#define RT_STRIDE 132

__device__ float g_hnorm[DCODES];
__device__ __align__(256) __nv_bfloat16 g_dh16[DCODES * CDIM];
__device__ __align__(256) __nv_bfloat16 g_dm16[DCODES * CDIM];

// ---------------- helpers ----------------
__device__ __forceinline__ uint32_t smem_u32(const void* p) {
    uint32_t a;
    asm("{ .reg .u64 t; cvta.to.shared.u64 t, %1; cvt.u32.u64 %0, t; }" : "=r"(a) : "l"(p));
    return a;
}
__device__ __forceinline__ void ldmx4(uint32_t r[4], uint32_t addr) {
    asm volatile("ldmatrix.sync.aligned.m8n8.x4.shared.b16 {%0,%1,%2,%3}, [%4];"
                 : "=r"(r[0]), "=r"(r[1]), "=r"(r[2]), "=r"(r[3]) : "r"(addr));
}
__device__ __forceinline__ void mma16816(float c[4], const uint32_t a[4], const uint32_t b[2]) {
    asm volatile("mma.sync.aligned.m16n8k16.row.col.f32.bf16.bf16.f32 "
                 "{%0,%1,%2,%3}, {%4,%5,%6,%7}, {%8,%9}, {%0,%1,%2,%3};"
                 : "+f"(c[0]), "+f"(c[1]), "+f"(c[2]), "+f"(c[3])
                 : "r"(a[0]), "r"(a[1]), "r"(a[2]), "r"(a[3]), "r"(b[0]), "r"(b[1]));
}
#define CPA16(dst, src) \
    asm volatile("cp.async.cg.shared.global [%0], [%1], 16;" :: "r"(dst), "l"(src) : "memory")
#define CPA_COMMIT() asm volatile("cp.async.commit_group;" ::: "memory")
#define CPA_WAIT0()  asm volatile("cp.async.wait_group 0;" ::: "memory")

// ---------------- prologue kernels ----------------
__global__ void vq_hnorm_kernel(const float* __restrict__ dict) {
    int d = blockIdx.x * blockDim.x + threadIdx.x;
    if (d < DCODES) {
        const float4* row = reinterpret_cast<const float4*>(dict + (size_t)d * CDIM);
        float s = 0.f;
#pragma unroll
        for (int q = 0; q < CDIM / 4; q++) {
            float4 v = row[q];
            s += v.x * v.x + v.y * v.y + v.z * v.z + v.w * v.w;
        }
        g_hnorm[d] = 0.5f * s;
    }
}

__global__ void vq_split_kernel(const float* __restrict__ dict) {
    int idx = blockIdx.x * blockDim.x + threadIdx.x;   // 0..65535
    int d = idx >> 7, j = idx & 127;
    float x0 = dict[(size_t)d * CDIM + 2 * j];
    float x1 = dict[(size_t)d * CDIM + 2 * j + 1];
    __nv_bfloat162 h2 = __float22bfloat162_rn(make_float2(x0, x1));
    float2 hf = __bfloat1622float2(h2);
    __nv_bfloat162 m2 = __float22bfloat162_rn(make_float2(x0 - hf.x, x1 - hf.y));
    reinterpret_cast<uint32_t*>(g_dh16)[d * 128 + j] = *reinterpret_cast<uint32_t*>(&h2);
    reinterpret_cast<uint32_t*>(g_dm16)[d * 128 + j] = *reinterpret_cast<uint32_t*>(&m2);
}

// ---------------- main kernel ----------------
__global__ __launch_bounds__(NTHREADS, 1)
void vq_main_kernel(const float* __restrict__ inputs,
                    const float* __restrict__ dict,
                    float* __restrict__ out) {
    extern __shared__ float smem[];
    const uint32_t sbase = smem_u32(smem);
    char* smc = reinterpret_cast<char*>(smem);
    int*   fidx  = reinterpret_cast<int*>(smc + OFF_FIDX);
    int*   sidxm = reinterpret_cast<int*>(smc + OFF_SIDXM);
    int*   flags = reinterpret_cast<int*>(smc + OFF_FLAGS);
    int*   flagn = reinterpret_cast<int*>(smc + OFF_FLAGN);

    const int tid = threadIdx.x;
    const int wid = tid >> 5, lane = tid & 31;
    const int wm = wid >> 2, wn = wid & 3;
    const int n = blockIdx.x >> 7, tt0 = (blockIdx.x & 127) << 7;
    const size_t E = (size_t)NBATCH * CDIM * TDIM;

    if (tid == 0) *flagn = 0;

    // ================= A build: load x slabs, transpose + split into Ah/Am =================
    {
        float* xsl = smem + OFF_B / 4;     // slab [64 c][128 t] fp32 in B region
        const int t = tid & 127, half = tid >> 7;
        for (int kc = 0; kc < 4; kc++) {
#pragma unroll
            for (int it = 0; it < 8; it++) {
                int j = tid + it * 256;
                int c = j >> 5, u = j & 31;
                const float* src = inputs + ((size_t)(n * CDIM + kc * 64 + c)) * TDIM + tt0 + u * 4;
                CPA16(sbase + OFF_B + c * 512 + u * 16, src);
            }
            CPA_COMMIT(); CPA_WAIT0();
            __syncthreads();
#pragma unroll
            for (int i = 0; i < 16; i++) {
                int c = half * 32 + 2 * i;
                float x0 = xsl[c * 128 + t];
                float x1 = xsl[(c + 1) * 128 + t];
                __nv_bfloat162 h2 = __float22bfloat162_rn(make_float2(x0, x1));
                float2 hf = __bfloat1622float2(h2);
                __nv_bfloat162 m2 = __float22bfloat162_rn(make_float2(x0 - hf.x, x1 - hf.y));
                *reinterpret_cast<uint32_t*>(smc + kc * AK + t * 144 + (kc * 0 + c) * 2) =
                    *reinterpret_cast<uint32_t*>(&h2);
                *reinterpret_cast<uint32_t*>(smc + OFF_AM + kc * AK + t * 144 + c * 2) =
                    *reinterpret_cast<uint32_t*>(&m2);
            }
            __syncthreads();
        }
    }

    // ================= mainloop =================
    // per-thread top-2 over 8 local t's
    float best[8], sec[8]; int ibest[8], isec[8];
#pragma unroll
    for (int i = 0; i < 8; i++) { best[i] = -3.0e38f; sec[i] = -3.0e38f; ibest[i] = 0x3fffffff; isec[i] = 0x3fffffff; }

    const uint32_t aHrow = sbase + (uint32_t)((wm * 64 + (lane & 15)) * 144 + (lane >> 4) * 16);
    const uint32_t aMrow = aHrow + OFF_AM;
    const uint32_t bRow  = (uint32_t)((wn * 32 + ((lane >> 4) & 1) * 8 + (lane & 7)) * 144 +
                                      ((lane >> 3) & 1) * 16);

#define STAGE_B(s_) do { \
    int nc_ = (s_) >> 2, kc_ = (s_) & 3; \
    uint32_t dstb = sbase + OFF_B + ((s_) & 1) * BSTAGE; \
    const __nv_bfloat16* sH = g_dh16 + (size_t)nc_ * 128 * CDIM + kc_ * 64; \
    const __nv_bfloat16* sM = g_dm16 + (size_t)nc_ * 128 * CDIM + kc_ * 64; \
    _Pragma("unroll") \
    for (int it = 0; it < 4; it++) { \
        int j = tid + it * 256; int d = j >> 3, u = j & 7; \
        CPA16(dstb + d * 144 + u * 16, sH + (size_t)d * CDIM + u * 8); \
        CPA16(dstb + BSTAGE / 2 + d * 144 + u * 16, sM + (size_t)d * CDIM + u * 8); \
    } \
    CPA_COMMIT(); \
} while (0)

    STAGE_B(0); CPA_WAIT0(); __syncthreads();

    float acc[4][4][4];
    for (int s = 0; s < 16; s++) {
        const int nc = s >> 2, kc = s & 3;
        if (kc == 0) {
#pragma unroll
            for (int mt = 0; mt < 4; mt++)
#pragma unroll
                for (int nt = 0; nt < 4; nt++)
#pragma unroll
                    for (int e = 0; e < 4; e++) acc[mt][nt][e] = 0.f;
        }
        if (s < 15) STAGE_B(s + 1);

        const uint32_t aH = aHrow + kc * AK;
        const uint32_t aM = aMrow + kc * AK;
        const uint32_t bb = sbase + OFF_B + (s & 1) * BSTAGE + bRow;
        const uint32_t bH = bb, bM = bb + BSTAGE / 2;

#pragma unroll
        for (int ks = 0; ks < 4; ks++) {
            const uint32_t koff = ks * 32;
            uint32_t ah[4][4], am[4][4], bh[4][2], bm[4][2];
#pragma unroll
            for (int mt = 0; mt < 4; mt++) ldmx4(ah[mt], aH + mt * 2304 + koff);
            {
                uint32_t tp[4];
                ldmx4(tp, bH + koff);        bh[0][0]=tp[0]; bh[0][1]=tp[1]; bh[1][0]=tp[2]; bh[1][1]=tp[3];
                ldmx4(tp, bH + 2304 + koff); bh[2][0]=tp[0]; bh[2][1]=tp[1]; bh[3][0]=tp[2]; bh[3][1]=tp[3];
            }
#pragma unroll
            for (int mt = 0; mt < 4; mt++)
#pragma unroll
                for (int nt = 0; nt < 4; nt++) mma16816(acc[mt][nt], ah[mt], bh[nt]);
            {
                uint32_t tp[4];
                ldmx4(tp, bM + koff);        bm[0][0]=tp[0]; bm[0][1]=tp[1]; bm[1][0]=tp[2]; bm[1][1]=tp[3];
                ldmx4(tp, bM + 2304 + koff); bm[2][0]=tp[0]; bm[2][1]=tp[1]; bm[3][0]=tp[2]; bm[3][1]=tp[3];
            }
#pragma unroll
            for (int mt = 0; mt < 4; mt++)
#pragma unroll
                for (int nt = 0; nt < 4; nt++) mma16816(acc[mt][nt], ah[mt], bm[nt]);
#pragma unroll
            for (int mt = 0; mt < 4; mt++) ldmx4(am[mt], aM + mt * 2304 + koff);
#pragma unroll
            for (int mt = 0; mt < 4; mt++)
#pragma unroll
                for (int nt = 0; nt < 4; nt++) mma16816(acc[mt][nt], am[mt], bh[nt]);
        }

        if (kc == 3) {
            const int dbase = nc * 128 + wn * 32 + (lane & 3) * 2;
#pragma unroll
            for (int mt = 0; mt < 4; mt++) {
#pragma unroll
                for (int rh = 0; rh < 2; rh++) {
                    const int li = mt * 2 + rh;
                    float b_ = best[li], s_ = sec[li]; int bi_ = ibest[li], si_ = isec[li];
#pragma unroll
                    for (int nt = 0; nt < 4; nt++) {
#pragma unroll
                        for (int cc = 0; cc < 2; cc++) {
                            const int d = dbase + nt * 8 + cc;
                            float v = acc[mt][nt][rh * 2 + cc] - g_hnorm[d];
                            if (v > b_)      { s_ = b_; si_ = bi_; b_ = v; bi_ = d; }
                            else if (v > s_) { s_ = v;  si_ = d; }
                        }
                    }
                    best[li] = b_; sec[li] = s_; ibest[li] = bi_; isec[li] = si_;
                }
            }
        }
        CPA_WAIT0();
        __syncthreads();
    }

    // ================= cross-thread top-2 merge =================
    {
        float* bestv = smem;                               // [128][16]
        float* secv  = smem + 2048;
        int*   ibv   = reinterpret_cast<int*>(smem + 4096);
        int*   isv   = reinterpret_cast<int*>(smem + 6144);
        const int slot = wn * 4 + (lane & 3);
#pragma unroll
        for (int mt = 0; mt < 4; mt++)
#pragma unroll
            for (int rh = 0; rh < 2; rh++) {
                const int li = mt * 2 + rh;
                const int t = wm * 64 + mt * 16 + (lane >> 2) + rh * 8;
                bestv[t * 16 + slot] = best[li];
                secv [t * 16 + slot] = sec[li];
                ibv  [t * 16 + slot] = ibest[li];
                isv  [t * 16 + slot] = isec[li];
            }
        __syncthreads();

        if (tid < BT) {
            float B = -3.0e38f, S = -3.0e38f; int I = 0x3fffffff, J = 0x3fffffff;
            for (int q = 0; q < 16; q++) {
                float b = bestv[tid * 16 + q], s2 = secv[tid * 16 + q];
                int   i = ibv[tid * 16 + q],   j2 = isv[tid * 16 + q];
                bool bw = (b > B) || (b == B && i < I);
                if (bw) {
                    bool c = (B > s2) || (B == s2 && I < j2);
                    S = c ? B : s2; J = c ? I : j2;
                    B = b; I = i;
                } else {
                    bool c = (b > S) || (b == S && i < J);
                    if (c) { S = b; J = i; }
                }
            }
            fidx[tid] = I; sidxm[tid] = J;
            if (B - S < MARGIN) { int p = atomicAdd(flagn, 1); flags[p] = tid; }
        }
    }
    __syncthreads();

    // ================= exact fp32 rescore for near-tie queries =================
    {
        const int nf = *flagn;
        for (int e = wid; e < nf; e += 8) {
            const int q = flags[e];
            const int i1 = fidx[q], i2 = sidxm[q];
            const float* xp = inputs + ((size_t)n * CDIM) * TDIM + tt0 + q;
            float p1 = 0.f, p2 = 0.f;
            for (int c = lane; c < CDIM; c += 32) {
                float xv = xp[(size_t)c * TDIM];
                p1 += xv * dict[(size_t)i1 * CDIM + c];
                p2 += xv * dict[(size_t)i2 * CDIM + c];
            }
#pragma unroll
            for (int o = 16; o; o >>= 1) {
                p1 += __shfl_xor_sync(0xffffffffu, p1, o);
                p2 += __shfl_xor_sync(0xffffffffu, p2, o);
            }
            if (lane == 0) {
                float c1 = p1 - g_hnorm[i1];
                float c2 = p2 - g_hnorm[i2];
                fidx[q] = (c2 > c1 || (c2 == c1 && i2 < i1)) ? i2 : i1;
            }
        }
    }
    __syncthreads();

    if (tid < BT)
        out[2 * E + (size_t)n * TDIM + tt0 + tid] = (float)fidx[tid];

    // ================= epilogue: gather selected rows, coalesced stores =================
    {
        float* rowsT = smem;   // [256][RT_STRIDE]
        for (int t = wid; t < BT; t += 8) {
            const float* drow = dict + (size_t)fidx[t] * CDIM;
#pragma unroll
            for (int q = 0; q < CDIM; q += 32)
                rowsT[(q + lane) * RT_STRIDE + t] = drow[q + lane];
        }
    }
    __syncthreads();
    {
        const float* rowsT = smem;
        float* out_e = out;
        float* out_p = out + E;
#pragma unroll
        for (int j = 0; j < 32; j++) {
            int c = wid + 8 * j;
            float4 v = *reinterpret_cast<const float4*>(&rowsT[c * RT_STRIDE + 4 * lane]);
            size_t o = ((size_t)n * CDIM + c) * TDIM + tt0 + 4 * lane;
            *reinterpret_cast<float4*>(out_e + o) = v;
            *reinterpret_cast<float4*>(out_p + o) = v;
        }
    }
}

// ---------------------------------------------------------------------------
extern "C" void kernel_launch(void* const* d_in, const int* in_sizes, int n_in,
                              void* d_out, int out_size) {
    const float* inputs = (const float*)d_in[0];
    const float* dict   = (const float*)d_in[1];
    float* out = (float*)d_out;

    cudaFuncSetAttribute(vq_main_kernel,
                         cudaFuncAttributeMaxDynamicSharedMemorySize, SMEM_BYTES);

    vq_hnorm_kernel<<<4, 128>>>(dict);
    vq_split_kernel<<<256, 256>>>(dict);
    vq_main_kernel<<<(NBATCH * TDIM) / BT, NTHREADS, SMEM_BYTES>>>(inputs, dict, out);
}

// round 5
// speedup vs baseline: 2.7214x; 1.2133x over previous
#include <cuda_runtime.h>
#include <cuda_bf16.h>
#include <cstdint>

#define NBATCH 8
#define CDIM   256
#define TDIM   16384
#define DCODES 512
#define BT     128
#define NTHREADS 256
#define MARGIN 0.125f

// ---- smem byte layout ----
// Ah[4 kchunks][128 t][72 bf16-slots]; row stride 144 B
#define AK        18432                 // 128*144
#define OFF_B     73728                 // B double buffer (= 4*AK)
#define BSTAGE    36864                 // per stage: Bh 18432 + Bm 18432
#define OFF_HN    147456                // float[512] hnorm copy
#define OFF_FIDX  149504
#define OFF_SIDXM 150016
#define OFF_FLAGS 150528
#define OFF_FLAGN 151040
#define SMEM_BYTES 151072
// overlays (A region, dead after mainloop): bestv[128][16]@0, secv@8192,
// ibv@16384, isv@24576; later rowsT[256][132] f32 @0 (135168 B < 147456)
#define RT_STRIDE 132

__device__ float g_hnorm[DCODES];
__device__ __align__(256) __nv_bfloat16 g_dh16[DCODES * CDIM];
__device__ __align__(256) __nv_bfloat16 g_dm16[DCODES * CDIM];

// ---------------- helpers ----------------
__device__ __forceinline__ uint32_t smem_u32(const void* p) {
    uint32_t a;
    asm("{ .reg .u64 t; cvta.to.shared.u64 t, %1; cvt.u32.u64 %0, t; }" : "=r"(a) : "l"(p));
    return a;
}
__device__ __forceinline__ void ldmx4(uint32_t r[4], uint32_t addr) {
    asm volatile("ldmatrix.sync.aligned.m8n8.x4.shared.b16 {%0,%1,%2,%3}, [%4];"
                 : "=r"(r[0]), "=r"(r[1]), "=r"(r[2]), "=r"(r[3]) : "r"(addr));
}
__device__ __forceinline__ void mma16816(float c[4], const uint32_t a[4], const uint32_t b[2]) {
    asm volatile("mma.sync.aligned.m16n8k16.row.col.f32.bf16.bf16.f32 "
                 "{%0,%1,%2,%3}, {%4,%5,%6,%7}, {%8,%9}, {%0,%1,%2,%3};"
                 : "+f"(c[0]), "+f"(c[1]), "+f"(c[2]), "+f"(c[3])
                 : "r"(a[0]), "r"(a[1]), "r"(a[2]), "r"(a[3]), "r"(b[0]), "r"(b[1]));
}
#define CPA16(dst, src) \
    asm volatile("cp.async.cg.shared.global [%0], [%1], 16;" :: "r"(dst), "l"(src) : "memory")
#define CPA_COMMIT() asm volatile("cp.async.commit_group;" ::: "memory")
#define CPA_WAIT0()  asm volatile("cp.async.wait_group 0;" ::: "memory")

// ---------------- prologue kernels ----------------
__global__ void vq_hnorm_kernel(const float* __restrict__ dict) {
    const int wid = threadIdx.x >> 5, lane = threadIdx.x & 31;
    const int d = blockIdx.x * 8 + wid;
    const float4* row = reinterpret_cast<const float4*>(dict + (size_t)d * CDIM);
    float s = 0.f;
#pragma unroll
    for (int j = 0; j < 2; j++) {
        float4 v = row[lane + 32 * j];
        s += v.x * v.x + v.y * v.y + v.z * v.z + v.w * v.w;
    }
#pragma unroll
    for (int o = 16; o; o >>= 1) s += __shfl_xor_sync(0xffffffffu, s, o);
    if (lane == 0) g_hnorm[d] = 0.5f * s;
}

__global__ void vq_split_kernel(const float* __restrict__ dict) {
    int idx = blockIdx.x * blockDim.x + threadIdx.x;   // 0..65535
    int d = idx >> 7, j = idx & 127;
    float x0 = dict[(size_t)d * CDIM + 2 * j];
    float x1 = dict[(size_t)d * CDIM + 2 * j + 1];
    __nv_bfloat162 h2 = __float22bfloat162_rn(make_float2(x0, x1));
    float2 hf = __bfloat1622float2(h2);
    __nv_bfloat162 m2 = __float22bfloat162_rn(make_float2(x0 - hf.x, x1 - hf.y));
    reinterpret_cast<uint32_t*>(g_dh16)[d * 128 + j] = *reinterpret_cast<uint32_t*>(&h2);
    reinterpret_cast<uint32_t*>(g_dm16)[d * 128 + j] = *reinterpret_cast<uint32_t*>(&m2);
}

// ---------------- main kernel ----------------
__global__ __launch_bounds__(NTHREADS, 1)
void vq_main_kernel(const float* __restrict__ inputs,
                    const float* __restrict__ dict,
                    float* __restrict__ out) {
    extern __shared__ float smem[];
    const uint32_t sbase = smem_u32(smem);
    char* smc = reinterpret_cast<char*>(smem);
    float* shn   = reinterpret_cast<float*>(smc + OFF_HN);
    int*   fidx  = reinterpret_cast<int*>(smc + OFF_FIDX);
    int*   sidxm = reinterpret_cast<int*>(smc + OFF_SIDXM);
    int*   flags = reinterpret_cast<int*>(smc + OFF_FLAGS);
    int*   flagn = reinterpret_cast<int*>(smc + OFF_FLAGN);

    const int tid = threadIdx.x;
    const int wid = tid >> 5, lane = tid & 31;
    const int wm = wid >> 2, wn = wid & 3;
    const int n = blockIdx.x >> 7, tt0 = (blockIdx.x & 127) << 7;
    const size_t E = (size_t)NBATCH * CDIM * TDIM;

    if (tid == 0) *flagn = 0;
    // hnorm copy to smem (used by argmax tail)
    shn[tid] = g_hnorm[tid];
    shn[tid + 256] = g_hnorm[tid + 256];

    // ================= A build: load x slabs, transpose + bf16-hi into Ah =================
    {
        float* xsl = smem + OFF_B / 4;     // slab [64 c][128 t] fp32 in B region
        const int t = tid & 127, half = tid >> 7;
        for (int kc = 0; kc < 4; kc++) {
#pragma unroll
            for (int it = 0; it < 8; it++) {
                int j = tid + it * 256;
                int c = j >> 5, u = j & 31;
                const float* src = inputs + ((size_t)(n * CDIM + kc * 64 + c)) * TDIM + tt0 + u * 4;
                CPA16(sbase + OFF_B + c * 512 + u * 16, src);
            }
            CPA_COMMIT(); CPA_WAIT0();
            __syncthreads();
#pragma unroll
            for (int i = 0; i < 16; i++) {
                int c = half * 32 + 2 * i;
                float x0 = xsl[c * 128 + t];
                float x1 = xsl[(c + 1) * 128 + t];
                __nv_bfloat162 h2 = __float22bfloat162_rn(make_float2(x0, x1));
                *reinterpret_cast<uint32_t*>(smc + kc * AK + t * 144 + c * 2) =
                    *reinterpret_cast<uint32_t*>(&h2);
            }
            __syncthreads();
        }
    }

    // ================= mainloop =================
    float best[8], sec[8]; int ibest[8], isec[8];
#pragma unroll
    for (int i = 0; i < 8; i++) { best[i] = -3.0e38f; sec[i] = -3.0e38f; ibest[i] = 0x3fffffff; isec[i] = 0x3fffffff; }

    const uint32_t aHrow = sbase + (uint32_t)((wm * 64 + (lane & 15)) * 144 + (lane >> 4) * 16);
    const uint32_t bRow  = (uint32_t)((wn * 32 + ((lane >> 4) & 1) * 8 + (lane & 7)) * 144 +
                                      ((lane >> 3) & 1) * 16);

#define STAGE_B(s_) do { \
    int nc_ = (s_) >> 2, kc_ = (s_) & 3; \
    uint32_t dstb = sbase + OFF_B + ((s_) & 1) * BSTAGE; \
    const __nv_bfloat16* sH = g_dh16 + (size_t)nc_ * 128 * CDIM + kc_ * 64; \
    const __nv_bfloat16* sM = g_dm16 + (size_t)nc_ * 128 * CDIM + kc_ * 64; \
    _Pragma("unroll") \
    for (int it = 0; it < 4; it++) { \
        int j = tid + it * 256; int d = j >> 3, u = j & 7; \
        CPA16(dstb + d * 144 + u * 16, sH + (size_t)d * CDIM + u * 8); \
        CPA16(dstb + BSTAGE / 2 + d * 144 + u * 16, sM + (size_t)d * CDIM + u * 8); \
    } \
    CPA_COMMIT(); \
} while (0)

    STAGE_B(0); CPA_WAIT0(); __syncthreads();

    float acc[4][4][4];
    for (int s = 0; s < 16; s++) {
        const int nc = s >> 2, kc = s & 3;
        if (kc == 0) {
#pragma unroll
            for (int mt = 0; mt < 4; mt++)
#pragma unroll
                for (int nt = 0; nt < 4; nt++)
#pragma unroll
                    for (int e = 0; e < 4; e++) acc[mt][nt][e] = 0.f;
        }
        if (s < 15) STAGE_B(s + 1);

        const uint32_t aH = aHrow + kc * AK;
        const uint32_t bb = sbase + OFF_B + (s & 1) * BSTAGE + bRow;
        const uint32_t bH = bb, bM = bb + BSTAGE / 2;

#pragma unroll
        for (int ks = 0; ks < 4; ks++) {
            const uint32_t koff = ks * 32;
            uint32_t ah[4][4], bh[4][2], bm[4][2];
#pragma unroll
            for (int mt = 0; mt < 4; mt++) ldmx4(ah[mt], aH + mt * 2304 + koff);
            {
                uint32_t tp[4];
                ldmx4(tp, bH + koff);        bh[0][0]=tp[0]; bh[0][1]=tp[1]; bh[1][0]=tp[2]; bh[1][1]=tp[3];
                ldmx4(tp, bH + 2304 + koff); bh[2][0]=tp[0]; bh[2][1]=tp[1]; bh[3][0]=tp[2]; bh[3][1]=tp[3];
            }
#pragma unroll
            for (int mt = 0; mt < 4; mt++)
#pragma unroll
                for (int nt = 0; nt < 4; nt++) mma16816(acc[mt][nt], ah[mt], bh[nt]);
            {
                uint32_t tp[4];
                ldmx4(tp, bM + koff);        bm[0][0]=tp[0]; bm[0][1]=tp[1]; bm[1][0]=tp[2]; bm[1][1]=tp[3];
                ldmx4(tp, bM + 2304 + koff); bm[2][0]=tp[0]; bm[2][1]=tp[1]; bm[3][0]=tp[2]; bm[3][1]=tp[3];
            }
#pragma unroll
            for (int mt = 0; mt < 4; mt++)
#pragma unroll
                for (int nt = 0; nt < 4; nt++) mma16816(acc[mt][nt], ah[mt], bm[nt]);
        }

        if (kc == 3) {
            const int dbase = nc * 128 + wn * 32 + (lane & 3) * 2;
#pragma unroll
            for (int mt = 0; mt < 4; mt++) {
#pragma unroll
                for (int rh = 0; rh < 2; rh++) {
                    const int li = mt * 2 + rh;
                    float b_ = best[li], s_ = sec[li]; int bi_ = ibest[li], si_ = isec[li];
#pragma unroll
                    for (int nt = 0; nt < 4; nt++) {
#pragma unroll
                        for (int cc = 0; cc < 2; cc++) {
                            const int d = dbase + nt * 8 + cc;
                            float v = acc[mt][nt][rh * 2 + cc] - shn[d];
                            if (v > b_)      { s_ = b_; si_ = bi_; b_ = v; bi_ = d; }
                            else if (v > s_) { s_ = v;  si_ = d; }
                        }
                    }
                    best[li] = b_; sec[li] = s_; ibest[li] = bi_; isec[li] = si_;
                }
            }
        }
        CPA_WAIT0();
        __syncthreads();
    }

    // ================= cross-thread top-2 merge =================
    {
        float* bestv = smem;                               // [128][16]
        float* secv  = smem + 2048;
        int*   ibv   = reinterpret_cast<int*>(smem + 4096);
        int*   isv   = reinterpret_cast<int*>(smem + 6144);
        const int slot = wn * 4 + (lane & 3);
#pragma unroll
        for (int mt = 0; mt < 4; mt++)
#pragma unroll
            for (int rh = 0; rh < 2; rh++) {
                const int li = mt * 2 + rh;
                const int t = wm * 64 + mt * 16 + (lane >> 2) + rh * 8;
                bestv[t * 16 + slot] = best[li];
                secv [t * 16 + slot] = sec[li];
                ibv  [t * 16 + slot] = ibest[li];
                isv  [t * 16 + slot] = isec[li];
            }
        __syncthreads();

        if (tid < BT) {
            float B = -3.0e38f, S = -3.0e38f; int I = 0x3fffffff, J = 0x3fffffff;
            for (int q = 0; q < 16; q++) {
                float b = bestv[tid * 16 + q], s2 = secv[tid * 16 + q];
                int   i = ibv[tid * 16 + q],   j2 = isv[tid * 16 + q];
                bool bw = (b > B) || (b == B && i < I);
                if (bw) {
                    bool c = (B > s2) || (B == s2 && I < j2);
                    S = c ? B : s2; J = c ? I : j2;
                    B = b; I = i;
                } else {
                    bool c = (b > S) || (b == S && i < J);
                    if (c) { S = b; J = i; }
                }
            }
            fidx[tid] = I; sidxm[tid] = J;
            if (B - S < MARGIN) { int p = atomicAdd(flagn, 1); flags[p] = tid; }
        }
    }
    __syncthreads();

    // ================= exact fp32 rescore for near-tie queries =================
    {
        const int nf = *flagn;
        for (int e = wid; e < nf; e += 8) {
            const int q = flags[e];
            const int i1 = fidx[q], i2 = sidxm[q];
            const float* xp = inputs + ((size_t)n * CDIM) * TDIM + tt0 + q;
            float p1 = 0.f, p2 = 0.f;
            for (int c = lane; c < CDIM; c += 32) {
                float xv = xp[(size_t)c * TDIM];
                p1 += xv * dict[(size_t)i1 * CDIM + c];
                p2 += xv * dict[(size_t)i2 * CDIM + c];
            }
#pragma unroll
            for (int o = 16; o; o >>= 1) {
                p1 += __shfl_xor_sync(0xffffffffu, p1, o);
                p2 += __shfl_xor_sync(0xffffffffu, p2, o);
            }
            if (lane == 0) {
                float c1 = p1 - g_hnorm[i1];
                float c2 = p2 - g_hnorm[i2];
                fidx[q] = (c2 > c1 || (c2 == c1 && i2 < i1)) ? i2 : i1;
            }
        }
    }
    __syncthreads();

    if (tid < BT)
        out[2 * E + (size_t)n * TDIM + tt0 + tid] = (float)fidx[tid];

    // ================= epilogue: gather selected rows, coalesced stores =================
    {
        float* rowsT = smem;   // [256][RT_STRIDE]
        for (int t = wid; t < BT; t += 8) {
            const float* drow = dict + (size_t)fidx[t] * CDIM;
#pragma unroll
            for (int q = 0; q < CDIM; q += 32)
                rowsT[(q + lane) * RT_STRIDE + t] = drow[q + lane];
        }
    }
    __syncthreads();
    {
        const float* rowsT = smem;
        float* out_e = out;
        float* out_p = out + E;
#pragma unroll
        for (int j = 0; j < 32; j++) {
            int c = wid + 8 * j;
            float4 v = *reinterpret_cast<const float4*>(&rowsT[c * RT_STRIDE + 4 * lane]);
            size_t o = ((size_t)n * CDIM + c) * TDIM + tt0 + 4 * lane;
            *reinterpret_cast<float4*>(out_e + o) = v;
            *reinterpret_cast<float4*>(out_p + o) = v;
        }
    }
}

// ---------------------------------------------------------------------------
extern "C" void kernel_launch(void* const* d_in, const int* in_sizes, int n_in,
                              void* d_out, int out_size) {
    const float* inputs = (const float*)d_in[0];
    const float* dict   = (const float*)d_in[1];
    float* out = (float*)d_out;

    cudaFuncSetAttribute(vq_main_kernel,
                         cudaFuncAttributeMaxDynamicSharedMemorySize, SMEM_BYTES);

    vq_hnorm_kernel<<<64, 256>>>(dict);
    vq_split_kernel<<<256, 256>>>(dict);
    vq_main_kernel<<<(NBATCH * TDIM) / BT, NTHREADS, SMEM_BYTES>>>(inputs, dict, out);
}